// round 16
// baseline (speedup 1.0000x reference)
#include <cuda_runtime.h>
#include <cuda_fp16.h>
#include <cstdint>

// ---------------------------------------------------------------------------
// MoESystem: gate (mean-pool MLP + softmax) -> route rows to one of two
// experts -> expert MLP [1536 -> 1024 -> 2].
//
//   1. prep_w_kernel      : zero counters + transpose W1 [K,N]->[N,K] fp16.
//                           64x32 tiles; 128 B coalesced reads AND writes.
//   2. gate_permute_kernel: single-pass gate; row held as fp16 regs (mean
//                           from fp32 loads), MLP gate, store to partitioned
//                           scratch with streaming cache hints. PDL: overlaps
//                           prep; sync before atomics.
//   3. gemm_kernel        : mma.sync m16n8k16 fp16 GEMM (fp32 accum),
//                           ldmatrix + fragment double-buffer, 3-stage
//                           cp.async ring, warp tile 32x64, 2 CTAs/SM.
//                           REGISTER-SATURATED (128 regs) -- DO NOT ADD STATE.
//                           PDL: overlaps gate tail; sync before g_cnt read.
//   4. finalize_kernel    : one thread per (row, j) output element -> 2x the
//                           latency-hiding parallelism of the row-per-thread
//                           version. PDL: sync at top.
//
// Smem tiles: 128 rows x 128 B (64 halfs, K-major). 16 B chunk j of row r
// stored at r*128 + ((j ^ (r&7))*16)  -> conflict-free LDSM (8-row spread).
// ---------------------------------------------------------------------------

#define T_DIM 48
#define D_DIM 32
#define TD 1536
#define H_DIM 1024
#define GH 128
#define MAXB 16384
#define W1SZ (TD * H_DIM)

#define BM 128
#define BN 128
#define BK 64                 // halfs of K per stage (= 128 B rows)
#define KB (TD / BK)          // 24  (divisible by 3)
#define NT (H_DIM / BN)       // 8

#define TILE_BYTES 16384      // 128 rows * 128 B
#define BIAS_OFF 0            // 128 floats
#define W2_OFF 512            // 256 floats
#define YSUM_OFF 1536         // 256 floats
#define A_OFF 3072
#define B_OFF (A_OFF + 3 * TILE_BYTES)
#define SMEM_BYTES (B_OFF + 3 * TILE_BYTES)   // 101376

// Scratch (device globals: allocation-free)
__device__ __half g_xp[(size_t)MAXB * TD];   // permuted rows, fp16
__device__ __half g_w1t[2 * W1SZ];           // W1^T fp16 [2][N][K]
__device__ float  g_ypart[NT * MAXB * 2];    // per-Ntile layer-2 partials
__device__ int    g_src[MAXB];               // permuted pos -> original row
__device__ int    g_cnt[2];                  // zeroed by prep_w each run

// ----------------------------- helpers -------------------------------------
__device__ __forceinline__ void cpa16(void* s, const void* g) {
    unsigned sa = (unsigned)__cvta_generic_to_shared(s);
    asm volatile("cp.async.cg.shared.global [%0], [%1], 16;" :: "r"(sa), "l"(g));
}
__device__ __forceinline__ void ldsm4(unsigned r[4], unsigned addr) {
    asm volatile(
        "ldmatrix.sync.aligned.m8n8.x4.shared.b16 {%0,%1,%2,%3}, [%4];"
        : "=r"(r[0]), "=r"(r[1]), "=r"(r[2]), "=r"(r[3]) : "r"(addr));
}
__device__ __forceinline__ void mma_f16(float c[4], unsigned a0, unsigned a1,
                                        unsigned a2, unsigned a3,
                                        unsigned b0, unsigned b1) {
    asm volatile(
        "mma.sync.aligned.m16n8k16.row.col.f32.f16.f16.f32 "
        "{%0,%1,%2,%3}, {%4,%5,%6,%7}, {%8,%9}, {%0,%1,%2,%3};"
        : "+f"(c[0]), "+f"(c[1]), "+f"(c[2]), "+f"(c[3])
        : "r"(a0), "r"(a1), "r"(a2), "r"(a3), "r"(b0), "r"(b1));
}
// streaming (evict-first) 128-bit load / 64-bit store
__device__ __forceinline__ float4 ldg_cs4(const float4* p) {
    float4 v;
    asm volatile("ld.global.cs.v4.f32 {%0,%1,%2,%3}, [%4];"
                 : "=f"(v.x), "=f"(v.y), "=f"(v.z), "=f"(v.w) : "l"(p));
    return v;
}
__device__ __forceinline__ void stg_cs2(uint2* p, uint2 v) {
    asm volatile("st.global.cs.v2.u32 [%0], {%1,%2};"
                 :: "l"(p), "r"(v.x), "r"(v.y) : "memory");
}

// ---------------------------------------------------------------------------
// Zero counters + transpose W1 [K=1536, N=1024] -> g_w1t[e][n][k] (fp16).
// 64(k) x 32(n) tiles, 256 threads: reads 128 B/warp, writes half2 -> 128 B/warp.
__global__ __launch_bounds__(256) void prep_w_kernel(
    const float* __restrict__ nW1, const float* __restrict__ aW1) {
    if (blockIdx.x == 0 && blockIdx.y == 0 && blockIdx.z == 0 &&
        threadIdx.x == 0) {
        g_cnt[0] = 0;
        g_cnt[1] = 0;
    }
    __shared__ float t[64][33];
    const int e = blockIdx.z;
    const float* W = e ? aW1 : nW1;
    const int k0 = blockIdx.x * 64, n0 = blockIdx.y * 32;
    const int tid = threadIdx.x;

#pragma unroll
    for (int q = 0; q < 8; q++) {
        int idx = tid + 256 * q;           // 0..2047
        int k = idx >> 5, n = idx & 31;
        t[k][n] = W[(size_t)(k0 + k) * H_DIM + n0 + n];
    }
    __syncthreads();

    __half* out = g_w1t + (size_t)e * W1SZ;
#pragma unroll
    for (int q = 0; q < 4; q++) {
        int j = tid + 256 * q;             // 0..1023
        int n = j >> 5, kk = j & 31;
        __half2 h = __floats2half2_rn(t[2 * kk][n], t[2 * kk + 1][n]);
        *(__half2*)(out + (size_t)(n0 + n) * TD + k0 + 2 * kk) = h;
    }
}

// ---------------------------------------------------------------------------
// One warp per sample, single pass over x. Row held as fp16 regs (24 regs);
// mean accumulated from the exact fp32 loads; MLP gate in fp32; then store.
// Lane j's float4 at slot j+32i always covers d = 4*(j&7)..+3.
// PDL secondary: pre-atomic work overlaps prep_w; grid-sync guards g_cnt.
__global__ __launch_bounds__(256) void gate_permute_kernel(
    const float* __restrict__ x, const float* __restrict__ gW1,
    const float* __restrict__ gb1, const float* __restrict__ gW2,
    const float* __restrict__ gb2, float* __restrict__ dout, int B,
    int out_size) {
    __shared__ float sW1[D_DIM * GH];
    __shared__ float sb1[GH];
    __shared__ float sW2[GH * 2];

    for (int i = threadIdx.x; i < D_DIM * GH; i += blockDim.x) sW1[i] = gW1[i];
    for (int i = threadIdx.x; i < GH; i += blockDim.x) sb1[i] = gb1[i];
    for (int i = threadIdx.x; i < GH * 2; i += blockDim.x) sW2[i] = gW2[i];
    __syncthreads();

    int warp = threadIdx.x >> 5;
    int lane = threadIdx.x & 31;
    int b = blockIdx.x * (blockDim.x >> 5) + warp;
    if (b >= B) {
        cudaGridDependencySynchronize();
        return;
    }

    const float4* src4 = (const float4*)(x + (size_t)b * TD);

    uint2 v16[12];                    // fp16 row state (24 regs)
    float m0 = 0.f, m1 = 0.f, m2 = 0.f, m3 = 0.f;
#pragma unroll
    for (int i = 0; i < 12; i++) {
        float4 v = ldg_cs4(src4 + lane + 32 * i);
        m0 += v.x;
        m1 += v.y;
        m2 += v.z;
        m3 += v.w;
        __half2 h01 = __floats2half2_rn(v.x, v.y);
        __half2 h23 = __floats2half2_rn(v.z, v.w);
        v16[i] = make_uint2(*(unsigned*)&h01, *(unsigned*)&h23);
    }
    // lanes {q, q+8, q+16, q+24} share the same d-range: reduce over them
#pragma unroll
    for (int off = 8; off <= 16; off <<= 1) {
        m0 += __shfl_xor_sync(0xffffffffu, m0, off);
        m1 += __shfl_xor_sync(0xffffffffu, m1, off);
        m2 += __shfl_xor_sync(0xffffffffu, m2, off);
        m3 += __shfl_xor_sync(0xffffffffu, m3, off);
    }
    // mean[d] for d = 4*(lane&7)+k lives in mk (all 4 replicas hold it)

    float a0 = sb1[lane], a1 = sb1[lane + 32], a2 = sb1[lane + 64],
          a3 = sb1[lane + 96];
#pragma unroll
    for (int d = 0; d < 32; d++) {
        float ms;
        switch (d & 3) {
            case 0: ms = __shfl_sync(0xffffffffu, m0, d >> 2); break;
            case 1: ms = __shfl_sync(0xffffffffu, m1, d >> 2); break;
            case 2: ms = __shfl_sync(0xffffffffu, m2, d >> 2); break;
            default: ms = __shfl_sync(0xffffffffu, m3, d >> 2); break;
        }
        float md = ms * (1.0f / 48.0f);
        a0 += md * sW1[d * GH + lane];
        a1 += md * sW1[d * GH + lane + 32];
        a2 += md * sW1[d * GH + lane + 64];
        a3 += md * sW1[d * GH + lane + 96];
    }
    a0 = fmaxf(a0, 0.f); a1 = fmaxf(a1, 0.f);
    a2 = fmaxf(a2, 0.f); a3 = fmaxf(a3, 0.f);

    float z0p = a0 * sW2[lane * 2] + a1 * sW2[(lane + 32) * 2] +
                a2 * sW2[(lane + 64) * 2] + a3 * sW2[(lane + 96) * 2];
    float z1p = a0 * sW2[lane * 2 + 1] + a1 * sW2[(lane + 32) * 2 + 1] +
                a2 * sW2[(lane + 64) * 2 + 1] + a3 * sW2[(lane + 96) * 2 + 1];
#pragma unroll
    for (int off = 16; off > 0; off >>= 1) {
        z0p += __shfl_xor_sync(0xffffffffu, z0p, off);
        z1p += __shfl_xor_sync(0xffffffffu, z1p, off);
    }
    float z0 = z0p + gb2[0];
    float z1 = z1p + gb2[1];

    float prob = 1.0f / (1.0f + expf(-fabsf(z1 - z0)));
    int dec = (z1 > z0) ? 1 : 0;
    bool abn = (prob >= 0.7f) && (dec == 1);

    // prep_w (primary) zeroes g_cnt: wait for it before the atomics.
    cudaGridDependencySynchronize();

    int p = 0;
    if (lane == 0) {
        if (abn) {
            int ia = atomicAdd(&g_cnt[1], 1);
            p = B - 1 - ia;
        } else {
            p = atomicAdd(&g_cnt[0], 1);
        }
        g_src[p] = b;
        if (2 * B + b < out_size) dout[2 * B + b] = (float)dec;
        if (3 * B + b < out_size) dout[3 * B + b] = prob;
    }
    p = __shfl_sync(0xffffffffu, p, 0);

    // store fp16 row from registers, streaming (read once later by cp.async)
    uint2* dst = (uint2*)(g_xp + (size_t)p * TD);
#pragma unroll
    for (int i = 0; i < 12; i++) stg_cs2(dst + lane + 32 * i, v16[i]);
}

// ---------------------------------------------------------------------------
// mma.sync fp16 GEMM with ldmatrix + fragment double-buffer. grid (NT, B/BM),
// 256 threads (8 warps, 4x2), 2 CTAs/SM. Warp tile 32x64. 3-stage ring.
// PDL secondary: address setup overlaps gate tail; sync before g_cnt read.
// REGISTER-SATURATED at 128 regs: do not add parameters or live state.
__global__ __launch_bounds__(256, 2) void gemm_kernel(
    const float* __restrict__ nb1, const float* __restrict__ ab1,
    const float* __restrict__ nW2, const float* __restrict__ aW2, int B) {
    extern __shared__ char smem[];
    float* sbias = (float*)(smem + BIAS_OFF);
    float* sw2 = (float*)(smem + W2_OFF);
    float* ysum = (float*)(smem + YSUM_OFF);

    const int tid = threadIdx.x;
    const int warp = tid >> 5;
    const int l = tid & 31;
    const int wm = warp >> 1;   // 0..3
    const int wn = warp & 1;    // 0..1
    const int qrow = l >> 2;    // 0..7
    const int qc = l & 3;       // 0..3

    const int nt = blockIdx.x;
    const int m0 = blockIdx.y * BM;
    const int n0 = nt * BN;

    // ldmatrix per-lane addressing (shared-space) -- safe pre-sync work
    const unsigned sb = (unsigned)__cvta_generic_to_shared(smem);
    const unsigned xr7 = (unsigned)((l & 7) * 16);
    const unsigned aRowBase =
        sb + A_OFF + (unsigned)((wm * 32 + ((l >> 3) & 1) * 8 + (l & 7)) * 128);
    const unsigned kbA = (unsigned)((l >> 4) * 16);
    const unsigned bRowBase =
        sb + B_OFF + (unsigned)((wn * 64 + ((l >> 4) & 1) * 8 + (l & 7)) * 128);
    const unsigned kbB = (unsigned)(((l >> 3) & 1) * 16);
    unsigned sA[4], sB[4];
#pragma unroll
    for (int s = 0; s < 4; s++) {
        sA[s] = ((unsigned)(32 * s) + kbA) ^ xr7;
        sB[s] = ((unsigned)(32 * s) + kbB) ^ xr7;
    }

    // gate (primary) fills g_cnt/g_xp: wait before reading them.
    cudaGridDependencySynchronize();

    const int split = g_cnt[0];
    const int e_lo = (m0 < split) ? 0 : 1;
    const int e_hi = (m0 + BM - 1 < split) ? 0 : 1;

    for (int e = e_lo; e <= e_hi; e++) {
        const __half* Wt = g_w1t + (size_t)e * W1SZ;
        const float* bias1 = e ? ab1 : nb1;
        const float* w2 = e ? aW2 : nW2;

        if (tid < 128) sbias[tid] = bias1[n0 + tid];
        if (tid < 256) sw2[tid] = w2[(size_t)n0 * 2 + tid];

        float c[2][8][4];
#pragma unroll
        for (int mi = 0; mi < 2; mi++)
#pragma unroll
            for (int ni = 0; ni < 8; ni++)
#pragma unroll
                for (int k = 0; k < 4; k++) c[mi][ni][k] = 0.f;

        // ---- tile loader: 128 rows x 128 B, chunk j -> j^(r&7) swizzle ----
        auto load_tile = [&](int i, int st) {
            const int k0 = i * BK;
            char* As_ = smem + A_OFF + st * TILE_BYTES;
            char* Bs_ = smem + B_OFF + st * TILE_BYTES;
#pragma unroll
            for (int q = 0; q < 4; q++) {
                int f = tid + 256 * q;
                int r = f >> 3, j = f & 7;
                int dst = r * 128 + ((j ^ (r & 7)) * 16);
                cpa16(As_ + dst, g_xp + (size_t)(m0 + r) * TD + k0 + j * 8);
                cpa16(Bs_ + dst, Wt + (size_t)(n0 + r) * TD + k0 + j * 8);
            }
            asm volatile("cp.async.commit_group;");
        };

        auto do_tile = [&](int i, int st) {
            if (i + 1 < KB)
                asm volatile("cp.async.wait_group 1;");
            else
                asm volatile("cp.async.wait_group 0;");
            __syncthreads();
            if (i + 2 < KB) load_tile(i + 2, (st + 2) % 3);

            const unsigned aT = aRowBase + (unsigned)(st * TILE_BYTES);
            const unsigned bT = bRowBase + (unsigned)(st * TILE_BYTES);

            // fragment double-buffer: LDSM for s+1 issued before MMAs of s
            unsigned a0[2][4], a1[2][4], bq[2][4][4];
            ldsm4(a0[0], aT + sA[0]);
            ldsm4(a1[0], aT + sA[0] + 2048);
#pragma unroll
            for (int nj = 0; nj < 4; nj++)
                ldsm4(bq[0][nj], bT + sB[0] + nj * 2048);
#pragma unroll
            for (int s = 0; s < 4; s++) {
                const int cur = s & 1, nxt = cur ^ 1;
                if (s < 3) {
                    ldsm4(a0[nxt], aT + sA[s + 1]);
                    ldsm4(a1[nxt], aT + sA[s + 1] + 2048);
#pragma unroll
                    for (int nj = 0; nj < 4; nj++)
                        ldsm4(bq[nxt][nj], bT + sB[s + 1] + nj * 2048);
                }
#pragma unroll
                for (int nj = 0; nj < 4; nj++) {
                    mma_f16(c[0][2 * nj], a0[cur][0], a0[cur][1], a0[cur][2],
                            a0[cur][3], bq[cur][nj][0], bq[cur][nj][1]);
                    mma_f16(c[1][2 * nj], a1[cur][0], a1[cur][1], a1[cur][2],
                            a1[cur][3], bq[cur][nj][0], bq[cur][nj][1]);
                    mma_f16(c[0][2 * nj + 1], a0[cur][0], a0[cur][1],
                            a0[cur][2], a0[cur][3], bq[cur][nj][2],
                            bq[cur][nj][3]);
                    mma_f16(c[1][2 * nj + 1], a1[cur][0], a1[cur][1],
                            a1[cur][2], a1[cur][3], bq[cur][nj][2],
                            bq[cur][nj][3]);
                }
            }
        };

        load_tile(0, 0);
        load_tile(1, 1);
        for (int ii = 0; ii < KB; ii += 3) {
            do_tile(ii + 0, 0);
            do_tile(ii + 1, 1);
            do_tile(ii + 2, 2);
        }

        // ---- epilogue: bias + relu + layer2, reduce to y[row][2] ----
        if (tid < 256) ysum[tid] = 0.f;
        __syncthreads();

#pragma unroll
        for (int mi = 0; mi < 2; mi++) {
            int rloc = wm * 32 + mi * 16 + qrow;
            float ylo0 = 0.f, ylo1 = 0.f, yhi0 = 0.f, yhi1 = 0.f;
#pragma unroll
            for (int ni = 0; ni < 8; ni++) {
                int col = wn * 64 + ni * 8 + 2 * qc;
                float h0 = fmaxf(c[mi][ni][0] + sbias[col], 0.f);
                float h1 = fmaxf(c[mi][ni][1] + sbias[col + 1], 0.f);
                float h2 = fmaxf(c[mi][ni][2] + sbias[col], 0.f);
                float h3 = fmaxf(c[mi][ni][3] + sbias[col + 1], 0.f);
                float w00 = sw2[col * 2], w01 = sw2[col * 2 + 1];
                float w10 = sw2[col * 2 + 2], w11 = sw2[col * 2 + 3];
                ylo0 += h0 * w00 + h1 * w10;
                ylo1 += h0 * w01 + h1 * w11;
                yhi0 += h2 * w00 + h3 * w10;
                yhi1 += h2 * w01 + h3 * w11;
            }
#pragma unroll
            for (int off = 1; off < 4; off <<= 1) {
                ylo0 += __shfl_xor_sync(0xffffffffu, ylo0, off);
                ylo1 += __shfl_xor_sync(0xffffffffu, ylo1, off);
                yhi0 += __shfl_xor_sync(0xffffffffu, yhi0, off);
                yhi1 += __shfl_xor_sync(0xffffffffu, yhi1, off);
            }
            if (qc == 0) {
                atomicAdd(&ysum[rloc * 2 + 0], ylo0);
                atomicAdd(&ysum[rloc * 2 + 1], ylo1);
                atomicAdd(&ysum[(rloc + 8) * 2 + 0], yhi0);
                atomicAdd(&ysum[(rloc + 8) * 2 + 1], yhi1);
            }
        }
        __syncthreads();

        {
            int row = tid >> 1;
            int j = tid & 1;
            int p = m0 + row;
            int rowExp = (p >= split) ? 1 : 0;
            if (rowExp == e)
                g_ypart[((size_t)nt * B + p) * 2 + j] = ysum[tid];
        }
        __syncthreads();
    }
}

// ---------------------------------------------------------------------------
// PDL secondary: sync at top (needs gemm's g_ypart + gate's g_src/g_cnt).
// One thread per (row p, output j): 2x parallelism vs row-per-thread; the
// per-thread chain is g_src + 8 scalar loads + 1 store.
__global__ __launch_bounds__(128) void finalize_kernel(
    const float* __restrict__ nb2, const float* __restrict__ ab2,
    float* __restrict__ dout, int B, int out_size) {
    cudaGridDependencySynchronize();
    int idx = blockIdx.x * blockDim.x + threadIdx.x;
    int p = idx >> 1;
    int j = idx & 1;
    if (p >= B) return;
    int split = g_cnt[0];
    int b = g_src[p];
    const float* b2 = (p < split) ? nb2 : ab2;
    float y = 0.f;
#pragma unroll
    for (int nt = 0; nt < NT; nt++)
        y += g_ypart[((size_t)nt * B + p) * 2 + j];
    if (b * 2 + j < out_size) dout[b * 2 + j] = y + b2[j];
}

// ---------------------------------------------------------------------------
extern "C" void kernel_launch(void* const* d_in, const int* in_sizes, int n_in,
                              void* d_out, int out_size) {
    const float* x = (const float*)d_in[0];
    const float* gW1 = (const float*)d_in[1];
    const float* gb1 = (const float*)d_in[2];
    const float* gW2 = (const float*)d_in[3];
    const float* gb2 = (const float*)d_in[4];
    const float* nW1 = (const float*)d_in[5];
    const float* nb1 = (const float*)d_in[6];
    const float* nW2 = (const float*)d_in[7];
    const float* nb2 = (const float*)d_in[8];
    const float* aW1 = (const float*)d_in[9];
    const float* ab1 = (const float*)d_in[10];
    const float* aW2 = (const float*)d_in[11];
    const float* ab2 = (const float*)d_in[12];

    int B = in_sizes[0] / TD;
    float* out = (float*)d_out;

    cudaFuncSetAttribute(gemm_kernel,
                         cudaFuncAttributeMaxDynamicSharedMemorySize,
                         SMEM_BYTES);

    // primary: prep (zeroes counters, transposes W1; coalesced both ways)
    prep_w_kernel<<<dim3(TD / 64, H_DIM / 32, 2), 256>>>(nW1, aW1);

    cudaLaunchAttribute attrs[1];
    attrs[0].id = cudaLaunchAttributeProgrammaticStreamSerialization;
    attrs[0].val.programmaticStreamSerializationAllowed = 1;

    cudaLaunchConfig_t cfg = {};
    cfg.attrs = attrs;
    cfg.numAttrs = 1;
    cfg.stream = 0;

    // gate: PDL over prep
    cfg.gridDim = dim3((B + 7) / 8);
    cfg.blockDim = dim3(256);
    cfg.dynamicSmemBytes = 0;
    cudaLaunchKernelEx(&cfg, gate_permute_kernel, x, gW1, gb1, gW2, gb2, out,
                       B, out_size);

    // gemm: PDL over gate
    cfg.gridDim = dim3(NT, B / BM);
    cfg.blockDim = dim3(256);
    cfg.dynamicSmemBytes = SMEM_BYTES;
    cudaLaunchKernelEx(&cfg, gemm_kernel, nb1, ab1, nW2, aW2, B);

    // finalize: PDL over gemm; one thread per output element (2*B threads)
    cfg.gridDim = dim3((2 * B + 127) / 128);
    cfg.blockDim = dim3(128);
    cfg.dynamicSmemBytes = 0;
    cudaLaunchKernelEx(&cfg, finalize_kernel, nb2, ab2, out, B, out_size);
}